// round 10
// baseline (speedup 1.0000x reference)
#include <cuda_runtime.h>
#include <cstdint>

#define TT  32
#define BB  16
#define KK  4
#define HH  512
#define VV  32000
#define BKX 64
#define G3  1536
#define EOS_ID 2

#define O1 16384000
#define O2 16392192
#define O3 16392256
#define O4 16392320

// ---------------- device state ----------------
__device__ float g_logits[(size_t)TT*BKX*VV];
__device__ float g_corr[TT*BKX];
__device__ float g_h[BKX*HH];
__device__ float g_hnew[BKX*HH];
__device__ int   g_inp[BKX];
__device__ float g_ss[BKX];
__device__ int   g_syms[TT*BKX];
__device__ int   g_preds[TT*BKX];
__device__ float g_scores[TT*BKX];
__device__ float g_hiddens[TT*BKX*HH];
__device__ float g_part[8*BKX*G3];
__device__ float g_tkv[BKX];
__device__ int   g_tksym[BKX];
__device__ int   g_tkpred[BKX];
__device__ int   g_src[TT*BKX];
__device__ int   g_seq[TT*BKX];
__device__ int   g_rowfin[TT*BB];
__device__ int   g_hcode[BB];

// ---------------- helpers ----------------
__device__ __forceinline__ unsigned long long ffma2(unsigned long long a,
                                                    unsigned long long b,
                                                    unsigned long long c){
    unsigned long long d;
    asm("fma.rn.f32x2 %0, %1, %2, %3;" : "=l"(d) : "l"(a), "l"(b), "l"(c));
    return d;
}
__device__ __forceinline__ unsigned long long dup2(float x){
    unsigned long long d; unsigned int xi = __float_as_uint(x);
    asm("mov.b64 %0, {%1, %2};" : "=l"(d) : "r"(xi), "r"(xi));
    return d;
}
__device__ __forceinline__ void unpack2(unsigned long long a, float& lo, float& hi){
    unsigned int l, h;
    asm("mov.b64 {%0, %1}, %2;" : "=r"(l), "=r"(h) : "l"(a));
    lo = __uint_as_float(l); hi = __uint_as_float(h);
}
__device__ __forceinline__ float neg_inf(){ return __int_as_float(0xff800000); }

// top-4 insert, order: value desc, index asc (jax.lax.top_k tie rule)
__device__ __forceinline__ void tk_insert(float* tv, int* ti, float val, int c){
    if (val > tv[3] || (val == tv[3] && c < ti[3])){
        tv[3] = val; ti[3] = c;
        #pragma unroll
        for (int j = 3; j > 0; j--){
            if (tv[j] > tv[j-1] || (tv[j] == tv[j-1] && ti[j] < ti[j-1])){
                float tf = tv[j]; tv[j] = tv[j-1]; tv[j-1] = tf;
                int   tq = ti[j]; ti[j] = ti[j-1]; ti[j-1] = tq;
            }
        }
    }
}
// sort 4 (value desc, index asc) via selection sort
__device__ __forceinline__ void sort4(float* v, int* id){
    #pragma unroll
    for (int i = 0; i < 4; i++){
        int best = i;
        #pragma unroll
        for (int j = i+1; j < 4; j++)
            if (v[j] > v[best] || (v[j] == v[best] && id[j] < id[best])) best = j;
        float tv = v[i]; v[i] = v[best]; v[best] = tv;
        int   tq = id[i]; id[i] = id[best]; id[best] = tq;
    }
}

// ---------------- init ----------------
__global__ void k_init(const float* __restrict__ enc_h){
    int i = blockIdx.x*blockDim.x + threadIdx.x;
    if (i < BKX*HH){
        int bk = i >> 9, u = i & (HH-1);
        g_h[i] = enc_h[(bk & (BB-1))*HH + u];
    }
    if (i < BKX){
        g_inp[i] = 1;
        g_ss[i]  = ((i & 3) == 0) ? 0.0f : neg_inf();
    }
}

// ---------------- GRU GEMM, split-K x4, 2 matrices ----------------
// grid 96 = 2 mats * 12 col-tiles(128) * 4 k-splits(128), 128 threads
__global__ void __launch_bounds__(128) k_gru_gemm(const float* __restrict__ E,
                                                  const float* __restrict__ Wih,
                                                  const float* __restrict__ Whh){
    __shared__ __align__(16) float a_t[128][68];
    int bid = blockIdx.x;
    int m   = bid / 48;
    int rem = bid % 48;
    int ct  = rem >> 2;
    int ks  = rem & 3;
    int c0  = ct * 128;
    int r0  = ks * 128;
    int tid = threadIdx.x;

    // stage transposed activations: conflict-free smem writes
    {
        int row = tid & 63;
        int rcb = tid >> 6;     // 0..1
        int sym = (m == 0) ? g_inp[row] : 0;
        for (int rc = rcb; rc < 128; rc += 2){
            float v;
            if (m == 0) v = E[(size_t)sym*HH + r0 + rc];
            else        v = g_h[row*HH + r0 + rc];
            a_t[rc][row] = v;
        }
    }
    __syncthreads();

    int col = c0 + tid;
    const float* W  = (m == 0) ? Wih : Whh;
    const float* wp = W + (size_t)r0*G3 + col;

    unsigned long long acc[32];
    #pragma unroll
    for (int q = 0; q < 32; q++) acc[q] = 0ULL;

    float wbuf[4];
    #pragma unroll
    for (int q = 0; q < 4; q++) wbuf[q] = wp[(size_t)q*G3];

    for (int r = 0; r < 128; r += 4){
        float wn[4];
        #pragma unroll
        for (int q = 0; q < 4; q++) wn[q] = wp[(size_t)((r+4+q) & 127)*G3];
        #pragma unroll
        for (int q = 0; q < 4; q++){
            unsigned long long w2 = dup2(wbuf[q]);
            const double2* ap = (const double2*)(&a_t[r+q][0]);
            #pragma unroll
            for (int p = 0; p < 16; p++){
                double2 d = ap[p];
                acc[2*p]   = ffma2(__double_as_longlong(d.x), w2, acc[2*p]);
                acc[2*p+1] = ffma2(__double_as_longlong(d.y), w2, acc[2*p+1]);
            }
        }
        #pragma unroll
        for (int q = 0; q < 4; q++) wbuf[q] = wn[q];
    }

    float* outp = g_part + (size_t)((m*4+ks)*BKX)*G3 + col;
    #pragma unroll
    for (int q = 0; q < 32; q++){
        float f0, f1; unpack2(acc[q], f0, f1);
        outp[(size_t)(2*q)*G3]   = f0;
        outp[(size_t)(2*q+1)*G3] = f1;
    }
}

// ---------------- GRU combine (gates) ----------------
__global__ void k_gru_combine(const float* __restrict__ bih, const float* __restrict__ bhh){
    int gid = blockIdx.x*256 + threadIdx.x;      // 32768
    if (gid >= BKX*HH) return;
    int bk = gid >> 9, u = gid & (HH-1);
    float gir = bih[u], giz = bih[HH+u], gin = bih[2*HH+u];
    float ghr = bhh[u], ghz = bhh[HH+u], ghn = bhh[2*HH+u];
    #pragma unroll
    for (int ks = 0; ks < 4; ks++){
        const float* p0 = g_part + (size_t)(ks*BKX + bk)*G3;
        const float* p1 = g_part + (size_t)((4+ks)*BKX + bk)*G3;
        gir += p0[u]; giz += p0[HH+u]; gin += p0[2*HH+u];
        ghr += p1[u]; ghz += p1[HH+u]; ghn += p1[2*HH+u];
    }
    float r = 1.0f/(1.0f + expf(-(gir + ghr)));
    float z = 1.0f/(1.0f + expf(-(giz + ghz)));
    float n = tanhf(gin + r*ghn);
    g_hnew[gid] = (1.0f - z)*n + z*g_h[gid];
}

// ---------------- logits GEMM: (64x512)@(512x32000) + bo ----------------
// grid 125, 256 threads, 1 column/thread, 64 rows as 32 f32x2 accumulators
__global__ void __launch_bounds__(256) k_logits(const float* __restrict__ Wo,
                                                const float* __restrict__ bo, int t){
    extern __shared__ float ht[];   // [512][68] transposed h_new
    int tid = threadIdx.x;
    {
        int row = tid & 63;
        int rcb = tid >> 6;         // 0..3
        for (int rc = rcb; rc < HH; rc += 4)
            ht[rc*68 + row] = g_hnew[row*HH + rc];
    }
    __syncthreads();

    int v = blockIdx.x*256 + tid;
    unsigned long long acc[32];
    #pragma unroll
    for (int q = 0; q < 32; q++) acc[q] = 0ULL;

    const float* wp = Wo + v;
    float wbuf[4];
    #pragma unroll
    for (int q = 0; q < 4; q++) wbuf[q] = wp[(size_t)q*VV];

    for (int r = 0; r < HH; r += 4){
        float wn[4];
        #pragma unroll
        for (int q = 0; q < 4; q++) wn[q] = wp[(size_t)((r+4+q) & (HH-1))*VV];
        #pragma unroll
        for (int q = 0; q < 4; q++){
            unsigned long long w2 = dup2(wbuf[q]);
            const double2* ap = (const double2*)(&ht[(r+q)*68]);
            #pragma unroll
            for (int p = 0; p < 16; p++){
                double2 d = ap[p];
                acc[2*p]   = ffma2(__double_as_longlong(d.x), w2, acc[2*p]);
                acc[2*p+1] = ffma2(__double_as_longlong(d.y), w2, acc[2*p+1]);
            }
        }
        #pragma unroll
        for (int q = 0; q < 4; q++) wbuf[q] = wn[q];
    }

    float bv = bo[v];
    float* gl = g_logits + (size_t)(t*BKX)*VV + v;
    #pragma unroll
    for (int q = 0; q < 32; q++){
        float f0, f1; unpack2(acc[q], f0, f1);
        gl[(size_t)(2*q)*VV]   = f0 + bv;
        gl[(size_t)(2*q+1)*VV] = f1 + bv;
    }
}

// ---------------- log-softmax correction per row ----------------
__global__ void __launch_bounds__(256) k_rowstats(int t){
    __shared__ float red[256];
    int row = blockIdx.x;
    int tid = threadIdx.x;
    const float* p = g_logits + (size_t)(t*BKX + row)*VV;
    float m = neg_inf();
    for (int v = tid; v < VV; v += 256) m = fmaxf(m, p[v]);
    red[tid] = m; __syncthreads();
    for (int s = 128; s > 0; s >>= 1){
        if (tid < s) red[tid] = fmaxf(red[tid], red[tid+s]);
        __syncthreads();
    }
    m = red[0]; __syncthreads();
    float sum = 0.0f;
    for (int v = tid; v < VV; v += 256) sum += expf(p[v] - m);
    red[tid] = sum; __syncthreads();
    for (int s = 128; s > 0; s >>= 1){
        if (tid < s) red[tid] += red[tid+s];
        __syncthreads();
    }
    if (tid == 0) g_corr[t*BKX + row] = m + logf(red[0]);
}

// ---------------- per-batch top-4 over K*V candidates ----------------
__global__ void __launch_bounds__(256) k_topk(int t){
    __shared__ float sv[1024];
    __shared__ int   si[1024];
    int b = blockIdx.x, tid = threadIdx.x;
    float tv[4]; int ti[4];
    #pragma unroll
    for (int i = 0; i < 4; i++){ tv[i] = neg_inf(); ti[i] = 0x7fffffff; }

    #pragma unroll
    for (int k = 0; k < KK; k++){
        int row = b*KK + k;
        float base = g_ss[row] - g_corr[t*BKX + row];
        const float* p = g_logits + (size_t)(t*BKX + row)*VV;
        for (int v = tid; v < VV; v += 256)
            tk_insert(tv, ti, base + p[v], k*VV + v);
    }
    #pragma unroll
    for (int i = 0; i < 4; i++){ sv[tid*4+i] = tv[i]; si[tid*4+i] = ti[i]; }
    __syncthreads();
    if (tid < 32){
        float mv[4]; int mi[4];
        #pragma unroll
        for (int i = 0; i < 4; i++){ mv[i] = neg_inf(); mi[i] = 0x7fffffff; }
        for (int q = tid*32; q < tid*32+32; q++) tk_insert(mv, mi, sv[q], si[q]);
        #pragma unroll
        for (int i = 0; i < 4; i++){ sv[tid*4+i] = mv[i]; si[tid*4+i] = mi[i]; }
    }
    __syncthreads();
    if (tid == 0){
        float fv[4]; int fi[4];
        #pragma unroll
        for (int i = 0; i < 4; i++){ fv[i] = neg_inf(); fi[i] = 0x7fffffff; }
        for (int q = 0; q < 128; q++) tk_insert(fv, fi, sv[q], si[q]);
        #pragma unroll
        for (int k = 0; k < 4; k++){
            g_tkv[b*KK+k]    = fv[k];
            g_tksym[b*KK+k]  = fi[k] % VV;
            g_tkpred[b*KK+k] = fi[k] / VV + b*KK;
        }
    }
}

// ---------------- beam selection / state update ----------------
__global__ void __launch_bounds__(128) k_select(int t){
    int j = blockIdx.x;
    int tid = threadIdx.x;
    int pred = g_tkpred[j];
    for (int u = tid; u < HH; u += 128){
        float hv = g_hnew[pred*HH + u];
        g_h[j*HH + u] = hv;
        g_hiddens[(size_t)(t*BKX + j)*HH + u] = hv;
    }
    if (tid == 0){
        int sym = g_tksym[j];
        float sc = g_tkv[j];
        g_syms[t*BKX + j]   = sym;
        g_preds[t*BKX + j]  = pred;
        g_scores[t*BKX + j] = sc;
        g_ss[j]  = (sym == EOS_ID) ? neg_inf() : sc;
        g_inp[j] = sym;
    }
}

// ---------------- backward trace + small outputs ----------------
__global__ void __launch_bounds__(64) k_backward(float* __restrict__ out){
    __shared__ float s_s[64]; __shared__ int s_len[64]; __shared__ int s_hc[64];
    __shared__ int s_tp[64]; __shared__ int s_eosf[16];
    __shared__ int sym[64], prd[64]; __shared__ float scr[64];
    __shared__ int sid[64]; __shared__ float s0v[64];
    __shared__ int re[64];

    int r  = threadIdx.x;
    int b  = r >> 2;
    int kk = r & 3;

    if (kk == 0){
        float v[4]; int id[4];
        #pragma unroll
        for (int k = 0; k < 4; k++){ v[k] = g_scores[(TT-1)*BKX + b*4 + k]; id[k] = k; }
        sort4(v, id);
        #pragma unroll
        for (int k = 0; k < 4; k++){ sid[b*4+k] = id[k]; s0v[b*4+k] = v[k]; }
        s_eosf[b] = 0;
    }
    __syncthreads();
    s_tp[r]  = b*4 + sid[r];
    s_s[r]   = s0v[r];
    s_len[r] = TT;
    s_hc[r]  = -1;
    __syncthreads();

    for (int t = TT-1; t >= 0; t--){
        sym[r] = g_syms[t*BKX + r];
        prd[r] = g_preds[t*BKX + r];
        scr[r] = g_scores[t*BKX + r];
        __syncthreads();

        int src    = s_tp[r];
        int my_src = src;
        int my_sym = sym[src];
        int my_np  = prd[src];

        int eosf = s_eosf[b];
        int cnt  = 0;
        #pragma unroll
        for (int kq = 0; kq < 4; kq++) cnt += (sym[b*4+kq] == EOS_ID);

        #pragma unroll
        for (int kj = 0; kj < 4; kj++){
            int j = b*4 + kj;
            if (sym[j] == EOS_ID){
                int higher = 0;
                for (int kq = kj+1; kq < 4; kq++) higher += (sym[b*4+kq] == EOS_ID);
                int occ   = eosf + higher;
                int res_k = 3 - (occ & 3);
                if (res_k == kk){
                    my_src = j; my_sym = sym[j]; my_np = prd[j];
                    s_hc[r]  = t*BKX + j;
                    s_s[r]   = scr[j];
                    s_len[r] = t + 1;
                }
            }
        }
        g_src[t*BKX + r] = my_src;
        g_seq[t*BKX + r] = my_sym;
        __syncthreads();
        s_tp[r] = my_np;
        if (kk == 0) s_eosf[b] = eosf + cnt;
        __syncthreads();
    }

    // final re-rank
    if (kk == 0){
        float v[4]; int id[4];
        #pragma unroll
        for (int k = 0; k < 4; k++){ v[k] = s_s[b*4+k]; id[k] = k; }
        sort4(v, id);
        #pragma unroll
        for (int k = 0; k < 4; k++){
            re[b*4+k] = b*4 + id[k];
            out[O2 + b*4+k] = v[k];
        }
    }
    __syncthreads();
    out[O3 + r] = (float)s_len[re[r]];
    for (int t = 0; t < TT; t++)
        out[O4 + (t*BB + b)*KK + kk] = (float)g_seq[t*BKX + re[r]];
    if (kk == 0){
        int r0 = re[b*4];
        for (int t = 0; t < TT; t++)
            g_rowfin[t*BB + b] = g_src[t*BKX + r0];
        g_hcode[b] = s_hc[r0];
    }
}

// ---------------- big outputs ----------------
__global__ void k_out_hidden(float* __restrict__ out){
    int b = blockIdx.x, u = threadIdx.x;
    int code = g_hcode[b];
    out[O1 + b*HH + u] = (code < 0) ? 0.0f : g_hiddens[(size_t)code*HH + u];
}

__global__ void __launch_bounds__(256) k_out_logits(float* __restrict__ out){
    size_t idx = (size_t)blockIdx.x*256 + threadIdx.x;
    if (idx >= (size_t)TT*BB*VV) return;
    int t = (int)(idx / ((size_t)BB*VV));
    int rem = (int)(idx - (size_t)t*BB*VV);
    int bb = rem / VV;
    int v  = rem - bb*VV;
    int row = g_rowfin[t*BB + bb];
    out[idx] = g_logits[(size_t)(t*BKX + row)*VV + v] - g_corr[t*BKX + row];
}

// ---------------- launch ----------------
extern "C" void kernel_launch(void* const* d_in, const int* in_sizes, int n_in,
                              void* d_out, int out_size){
    const float* enc_h = (const float*)d_in[0];
    const float* E     = (const float*)d_in[1];
    const float* Wih   = (const float*)d_in[2];
    const float* Whh   = (const float*)d_in[3];
    const float* bih   = (const float*)d_in[4];
    const float* bhh   = (const float*)d_in[5];
    const float* Wo    = (const float*)d_in[6];
    const float* bo    = (const float*)d_in[7];
    float* out = (float*)d_out;

    const int LOGITS_SMEM = HH*68*sizeof(float);   // 139264
    cudaFuncSetAttribute(k_logits, cudaFuncAttributeMaxDynamicSharedMemorySize, LOGITS_SMEM);

    k_init<<<128, 256>>>(enc_h);
    for (int t = 0; t < TT; t++){
        k_gru_gemm<<<96, 128>>>(E, Wih, Whh);
        k_gru_combine<<<128, 256>>>(bih, bhh);
        k_logits<<<125, 256, LOGITS_SMEM>>>(Wo, bo, t);
        k_rowstats<<<64, 256>>>(t);
        k_topk<<<16, 256>>>(t);
        k_select<<<64, 128>>>(t);
    }
    k_backward<<<1, 64>>>(out);
    k_out_hidden<<<BB, HH>>>(out);
    k_out_logits<<<(TT*BB*VV + 255)/256, 256>>>(out);
}

// round 11
// speedup vs baseline: 1.0002x; 1.0002x over previous
#include <cuda_runtime.h>
#include <cstdint>

#define TT  32
#define BB  16
#define KK  4
#define HH  512
#define VV  32000
#define BKX 64
#define G3  1536
#define EOS_ID 2

#define O1 16384000
#define O2 16392192
#define O3 16392256
#define O4 16392320

// ---------------- device state ----------------
__device__ float g_logits[(size_t)TT*BKX*VV];
__device__ float g_corr[TT*BKX];
__device__ float g_h[BKX*HH];
__device__ float g_hnew[BKX*HH];
__device__ int   g_inp[BKX];
__device__ float g_ss[BKX];
__device__ int   g_syms[TT*BKX];
__device__ int   g_preds[TT*BKX];
__device__ float g_scores[TT*BKX];
__device__ float g_hiddens[TT*BKX*HH];
__device__ float g_part[8*BKX*G3];
__device__ float g_tkv[BKX];
__device__ int   g_tksym[BKX];
__device__ int   g_tkpred[BKX];
__device__ int   g_src[TT*BKX];
__device__ int   g_seq[TT*BKX];
__device__ int   g_rowfin[TT*BB];
__device__ int   g_hcode[BB];

// ---------------- helpers ----------------
__device__ __forceinline__ unsigned long long ffma2(unsigned long long a,
                                                    unsigned long long b,
                                                    unsigned long long c){
    unsigned long long d;
    asm("fma.rn.f32x2 %0, %1, %2, %3;" : "=l"(d) : "l"(a), "l"(b), "l"(c));
    return d;
}
__device__ __forceinline__ unsigned long long dup2(float x){
    unsigned long long d; unsigned int xi = __float_as_uint(x);
    asm("mov.b64 %0, {%1, %2};" : "=l"(d) : "r"(xi), "r"(xi));
    return d;
}
__device__ __forceinline__ void unpack2(unsigned long long a, float& lo, float& hi){
    unsigned int l, h;
    asm("mov.b64 {%0, %1}, %2;" : "=r"(l), "=r"(h) : "l"(a));
    lo = __uint_as_float(l); hi = __uint_as_float(h);
}
__device__ __forceinline__ float neg_inf(){ return __int_as_float(0xff800000); }

// top-4 insert, order: value desc, index asc (jax.lax.top_k tie rule)
__device__ __forceinline__ void tk_insert(float* tv, int* ti, float val, int c){
    if (val > tv[3] || (val == tv[3] && c < ti[3])){
        tv[3] = val; ti[3] = c;
        #pragma unroll
        for (int j = 3; j > 0; j--){
            if (tv[j] > tv[j-1] || (tv[j] == tv[j-1] && ti[j] < ti[j-1])){
                float tf = tv[j]; tv[j] = tv[j-1]; tv[j-1] = tf;
                int   tq = ti[j]; ti[j] = ti[j-1]; ti[j-1] = tq;
            }
        }
    }
}
// sort 4 (value desc, index asc) via selection sort
__device__ __forceinline__ void sort4(float* v, int* id){
    #pragma unroll
    for (int i = 0; i < 4; i++){
        int best = i;
        #pragma unroll
        for (int j = i+1; j < 4; j++)
            if (v[j] > v[best] || (v[j] == v[best] && id[j] < id[best])) best = j;
        float tv = v[i]; v[i] = v[best]; v[best] = tv;
        int   tq = id[i]; id[i] = id[best]; id[best] = tq;
    }
}

// ---------------- init ----------------
__global__ void k_init(const float* __restrict__ enc_h){
    int i = blockIdx.x*blockDim.x + threadIdx.x;
    if (i < BKX*HH){
        int bk = i >> 9, u = i & (HH-1);
        g_h[i] = enc_h[(bk & (BB-1))*HH + u];
    }
    if (i < BKX){
        g_inp[i] = 1;
        g_ss[i]  = ((i & 3) == 0) ? 0.0f : neg_inf();
    }
}

// ---------------- GRU GEMM, split-K x4, 2 matrices ----------------
// grid 96 = 2 mats * 12 col-tiles(128) * 4 k-splits(128), 128 threads
__global__ void __launch_bounds__(128) k_gru_gemm(const float* __restrict__ E,
                                                  const float* __restrict__ Wih,
                                                  const float* __restrict__ Whh){
    __shared__ __align__(16) float a_t[128][68];
    int bid = blockIdx.x;
    int m   = bid / 48;
    int rem = bid % 48;
    int ct  = rem >> 2;
    int ks  = rem & 3;
    int c0  = ct * 128;
    int r0  = ks * 128;
    int tid = threadIdx.x;

    // stage transposed activations: conflict-free smem writes
    {
        int row = tid & 63;
        int rcb = tid >> 6;     // 0..1
        int sym = (m == 0) ? g_inp[row] : 0;
        for (int rc = rcb; rc < 128; rc += 2){
            float v;
            if (m == 0) v = E[(size_t)sym*HH + r0 + rc];
            else        v = g_h[row*HH + r0 + rc];
            a_t[rc][row] = v;
        }
    }
    __syncthreads();

    int col = c0 + tid;
    const float* W  = (m == 0) ? Wih : Whh;
    const float* wp = W + (size_t)r0*G3 + col;

    unsigned long long acc[32];
    #pragma unroll
    for (int q = 0; q < 32; q++) acc[q] = 0ULL;

    float wbuf[4];
    #pragma unroll
    for (int q = 0; q < 4; q++) wbuf[q] = wp[(size_t)q*G3];

    for (int r = 0; r < 128; r += 4){
        float wn[4];
        #pragma unroll
        for (int q = 0; q < 4; q++) wn[q] = wp[(size_t)((r+4+q) & 127)*G3];
        #pragma unroll
        for (int q = 0; q < 4; q++){
            unsigned long long w2 = dup2(wbuf[q]);
            const double2* ap = (const double2*)(&a_t[r+q][0]);
            #pragma unroll
            for (int p = 0; p < 16; p++){
                double2 d = ap[p];
                acc[2*p]   = ffma2(__double_as_longlong(d.x), w2, acc[2*p]);
                acc[2*p+1] = ffma2(__double_as_longlong(d.y), w2, acc[2*p+1]);
            }
        }
        #pragma unroll
        for (int q = 0; q < 4; q++) wbuf[q] = wn[q];
    }

    float* outp = g_part + (size_t)((m*4+ks)*BKX)*G3 + col;
    #pragma unroll
    for (int q = 0; q < 32; q++){
        float f0, f1; unpack2(acc[q], f0, f1);
        outp[(size_t)(2*q)*G3]   = f0;
        outp[(size_t)(2*q+1)*G3] = f1;
    }
}

// ---------------- GRU combine (gates) ----------------
__global__ void k_gru_combine(const float* __restrict__ bih, const float* __restrict__ bhh){
    int gid = blockIdx.x*256 + threadIdx.x;      // 32768
    if (gid >= BKX*HH) return;
    int bk = gid >> 9, u = gid & (HH-1);
    float gir = bih[u], giz = bih[HH+u], gin = bih[2*HH+u];
    float ghr = bhh[u], ghz = bhh[HH+u], ghn = bhh[2*HH+u];
    #pragma unroll
    for (int ks = 0; ks < 4; ks++){
        const float* p0 = g_part + (size_t)(ks*BKX + bk)*G3;
        const float* p1 = g_part + (size_t)((4+ks)*BKX + bk)*G3;
        gir += p0[u]; giz += p0[HH+u]; gin += p0[2*HH+u];
        ghr += p1[u]; ghz += p1[HH+u]; ghn += p1[2*HH+u];
    }
    float r = 1.0f/(1.0f + expf(-(gir + ghr)));
    float z = 1.0f/(1.0f + expf(-(giz + ghz)));
    float n = tanhf(gin + r*ghn);
    g_hnew[gid] = (1.0f - z)*n + z*g_h[gid];
}

// ---------------- logits GEMM: (64x512)@(512x32000) + bo ----------------
// grid 125, 256 threads, 1 column/thread, 64 rows as 32 f32x2 accumulators
__global__ void __launch_bounds__(256) k_logits(const float* __restrict__ Wo,
                                                const float* __restrict__ bo, int t){
    extern __shared__ float ht[];   // [512][68] transposed h_new
    int tid = threadIdx.x;
    {
        int row = tid & 63;
        int rcb = tid >> 6;         // 0..3
        for (int rc = rcb; rc < HH; rc += 4)
            ht[rc*68 + row] = g_hnew[row*HH + rc];
    }
    __syncthreads();

    int v = blockIdx.x*256 + tid;
    unsigned long long acc[32];
    #pragma unroll
    for (int q = 0; q < 32; q++) acc[q] = 0ULL;

    const float* wp = Wo + v;
    float wbuf[4];
    #pragma unroll
    for (int q = 0; q < 4; q++) wbuf[q] = wp[(size_t)q*VV];

    for (int r = 0; r < HH; r += 4){
        float wn[4];
        #pragma unroll
        for (int q = 0; q < 4; q++) wn[q] = wp[(size_t)((r+4+q) & (HH-1))*VV];
        #pragma unroll
        for (int q = 0; q < 4; q++){
            unsigned long long w2 = dup2(wbuf[q]);
            const double2* ap = (const double2*)(&ht[(r+q)*68]);
            #pragma unroll
            for (int p = 0; p < 16; p++){
                double2 d = ap[p];
                acc[2*p]   = ffma2(__double_as_longlong(d.x), w2, acc[2*p]);
                acc[2*p+1] = ffma2(__double_as_longlong(d.y), w2, acc[2*p+1]);
            }
        }
        #pragma unroll
        for (int q = 0; q < 4; q++) wbuf[q] = wn[q];
    }

    float bv = bo[v];
    float* gl = g_logits + (size_t)(t*BKX)*VV + v;
    #pragma unroll
    for (int q = 0; q < 32; q++){
        float f0, f1; unpack2(acc[q], f0, f1);
        gl[(size_t)(2*q)*VV]   = f0 + bv;
        gl[(size_t)(2*q+1)*VV] = f1 + bv;
    }
}

// ---------------- log-softmax correction per row ----------------
__global__ void __launch_bounds__(256) k_rowstats(int t){
    __shared__ float red[256];
    int row = blockIdx.x;
    int tid = threadIdx.x;
    const float* p = g_logits + (size_t)(t*BKX + row)*VV;
    float m = neg_inf();
    for (int v = tid; v < VV; v += 256) m = fmaxf(m, p[v]);
    red[tid] = m; __syncthreads();
    for (int s = 128; s > 0; s >>= 1){
        if (tid < s) red[tid] = fmaxf(red[tid], red[tid+s]);
        __syncthreads();
    }
    m = red[0]; __syncthreads();
    float sum = 0.0f;
    for (int v = tid; v < VV; v += 256) sum += expf(p[v] - m);
    red[tid] = sum; __syncthreads();
    for (int s = 128; s > 0; s >>= 1){
        if (tid < s) red[tid] += red[tid+s];
        __syncthreads();
    }
    if (tid == 0) g_corr[t*BKX + row] = m + logf(red[0]);
}

// ---------------- per-batch top-4 over K*V candidates ----------------
__global__ void __launch_bounds__(256) k_topk(int t){
    __shared__ float sv[1024];
    __shared__ int   si[1024];
    int b = blockIdx.x, tid = threadIdx.x;
    float tv[4]; int ti[4];
    #pragma unroll
    for (int i = 0; i < 4; i++){ tv[i] = neg_inf(); ti[i] = 0x7fffffff; }

    #pragma unroll
    for (int k = 0; k < KK; k++){
        int row = b*KK + k;
        float base = g_ss[row] - g_corr[t*BKX + row];
        const float* p = g_logits + (size_t)(t*BKX + row)*VV;
        for (int v = tid; v < VV; v += 256)
            tk_insert(tv, ti, base + p[v], k*VV + v);
    }
    #pragma unroll
    for (int i = 0; i < 4; i++){ sv[tid*4+i] = tv[i]; si[tid*4+i] = ti[i]; }
    __syncthreads();
    if (tid < 32){
        float mv[4]; int mi[4];
        #pragma unroll
        for (int i = 0; i < 4; i++){ mv[i] = neg_inf(); mi[i] = 0x7fffffff; }
        for (int q = tid*32; q < tid*32+32; q++) tk_insert(mv, mi, sv[q], si[q]);
        #pragma unroll
        for (int i = 0; i < 4; i++){ sv[tid*4+i] = mv[i]; si[tid*4+i] = mi[i]; }
    }
    __syncthreads();
    if (tid == 0){
        float fv[4]; int fi[4];
        #pragma unroll
        for (int i = 0; i < 4; i++){ fv[i] = neg_inf(); fi[i] = 0x7fffffff; }
        for (int q = 0; q < 128; q++) tk_insert(fv, fi, sv[q], si[q]);
        #pragma unroll
        for (int k = 0; k < 4; k++){
            g_tkv[b*KK+k]    = fv[k];
            g_tksym[b*KK+k]  = fi[k] % VV;
            g_tkpred[b*KK+k] = fi[k] / VV + b*KK;
        }
    }
}

// ---------------- beam selection / state update ----------------
__global__ void __launch_bounds__(128) k_select(int t){
    int j = blockIdx.x;
    int tid = threadIdx.x;
    int pred = g_tkpred[j];
    for (int u = tid; u < HH; u += 128){
        float hv = g_hnew[pred*HH + u];
        g_h[j*HH + u] = hv;
        g_hiddens[(size_t)(t*BKX + j)*HH + u] = hv;
    }
    if (tid == 0){
        int sym = g_tksym[j];
        float sc = g_tkv[j];
        g_syms[t*BKX + j]   = sym;
        g_preds[t*BKX + j]  = pred;
        g_scores[t*BKX + j] = sc;
        g_ss[j]  = (sym == EOS_ID) ? neg_inf() : sc;
        g_inp[j] = sym;
    }
}

// ---------------- backward trace + small outputs ----------------
__global__ void __launch_bounds__(64) k_backward(float* __restrict__ out){
    __shared__ float s_s[64]; __shared__ int s_len[64]; __shared__ int s_hc[64];
    __shared__ int s_tp[64]; __shared__ int s_eosf[16];
    __shared__ int sym[64], prd[64]; __shared__ float scr[64];
    __shared__ int sid[64]; __shared__ float s0v[64];
    __shared__ int re[64];

    int r  = threadIdx.x;
    int b  = r >> 2;
    int kk = r & 3;

    if (kk == 0){
        float v[4]; int id[4];
        #pragma unroll
        for (int k = 0; k < 4; k++){ v[k] = g_scores[(TT-1)*BKX + b*4 + k]; id[k] = k; }
        sort4(v, id);
        #pragma unroll
        for (int k = 0; k < 4; k++){ sid[b*4+k] = id[k]; s0v[b*4+k] = v[k]; }
        s_eosf[b] = 0;
    }
    __syncthreads();
    s_tp[r]  = b*4 + sid[r];
    s_s[r]   = s0v[r];
    s_len[r] = TT;
    s_hc[r]  = -1;
    __syncthreads();

    for (int t = TT-1; t >= 0; t--){
        sym[r] = g_syms[t*BKX + r];
        prd[r] = g_preds[t*BKX + r];
        scr[r] = g_scores[t*BKX + r];
        __syncthreads();

        int src    = s_tp[r];
        int my_src = src;
        int my_sym = sym[src];
        int my_np  = prd[src];

        int eosf = s_eosf[b];
        int cnt  = 0;
        #pragma unroll
        for (int kq = 0; kq < 4; kq++) cnt += (sym[b*4+kq] == EOS_ID);

        #pragma unroll
        for (int kj = 0; kj < 4; kj++){
            int j = b*4 + kj;
            if (sym[j] == EOS_ID){
                int higher = 0;
                for (int kq = kj+1; kq < 4; kq++) higher += (sym[b*4+kq] == EOS_ID);
                int occ   = eosf + higher;
                int res_k = 3 - (occ & 3);
                if (res_k == kk){
                    my_src = j; my_sym = sym[j]; my_np = prd[j];
                    s_hc[r]  = t*BKX + j;
                    s_s[r]   = scr[j];
                    s_len[r] = t + 1;
                }
            }
        }
        g_src[t*BKX + r] = my_src;
        g_seq[t*BKX + r] = my_sym;
        __syncthreads();
        s_tp[r] = my_np;
        if (kk == 0) s_eosf[b] = eosf + cnt;
        __syncthreads();
    }

    // final re-rank
    if (kk == 0){
        float v[4]; int id[4];
        #pragma unroll
        for (int k = 0; k < 4; k++){ v[k] = s_s[b*4+k]; id[k] = k; }
        sort4(v, id);
        #pragma unroll
        for (int k = 0; k < 4; k++){
            re[b*4+k] = b*4 + id[k];
            out[O2 + b*4+k] = v[k];
        }
    }
    __syncthreads();
    out[O3 + r] = (float)s_len[re[r]];
    for (int t = 0; t < TT; t++)
        out[O4 + (t*BB + b)*KK + kk] = (float)g_seq[t*BKX + re[r]];
    if (kk == 0){
        int r0 = re[b*4];
        for (int t = 0; t < TT; t++)
            g_rowfin[t*BB + b] = g_src[t*BKX + r0];
        g_hcode[b] = s_hc[r0];
    }
}

// ---------------- big outputs ----------------
__global__ void k_out_hidden(float* __restrict__ out){
    int b = blockIdx.x, u = threadIdx.x;
    int code = g_hcode[b];
    out[O1 + b*HH + u] = (code < 0) ? 0.0f : g_hiddens[(size_t)code*HH + u];
}

__global__ void __launch_bounds__(256) k_out_logits(float* __restrict__ out){
    size_t idx = (size_t)blockIdx.x*256 + threadIdx.x;
    if (idx >= (size_t)TT*BB*VV) return;
    int t = (int)(idx / ((size_t)BB*VV));
    int rem = (int)(idx - (size_t)t*BB*VV);
    int bb = rem / VV;
    int v  = rem - bb*VV;
    int row = g_rowfin[t*BB + bb];
    out[idx] = g_logits[(size_t)(t*BKX + row)*VV + v] - g_corr[t*BKX + row];
}

// ---------------- launch ----------------
extern "C" void kernel_launch(void* const* d_in, const int* in_sizes, int n_in,
                              void* d_out, int out_size){
    const float* enc_h = (const float*)d_in[0];
    const float* E     = (const float*)d_in[1];
    const float* Wih   = (const float*)d_in[2];
    const float* Whh   = (const float*)d_in[3];
    const float* bih   = (const float*)d_in[4];
    const float* bhh   = (const float*)d_in[5];
    const float* Wo    = (const float*)d_in[6];
    const float* bo    = (const float*)d_in[7];
    float* out = (float*)d_out;

    const int LOGITS_SMEM = HH*68*sizeof(float);   // 139264
    cudaFuncSetAttribute(k_logits, cudaFuncAttributeMaxDynamicSharedMemorySize, LOGITS_SMEM);

    k_init<<<128, 256>>>(enc_h);
    for (int t = 0; t < TT; t++){
        k_gru_gemm<<<96, 128>>>(E, Wih, Whh);
        k_gru_combine<<<128, 256>>>(bih, bhh);
        k_logits<<<125, 256, LOGITS_SMEM>>>(Wo, bo, t);
        k_rowstats<<<64, 256>>>(t);
        k_topk<<<16, 256>>>(t);
        k_select<<<64, 128>>>(t);
    }
    k_backward<<<1, 64>>>(out);
    k_out_hidden<<<BB, HH>>>(out);
    k_out_logits<<<(TT*BB*VV + 255)/256, 256>>>(out);
}

// round 12
// speedup vs baseline: 1.0067x; 1.0065x over previous
#include <cuda_runtime.h>
#include <cstdint>

#define TT  32
#define BB  16
#define KK  4
#define HH  512
#define VV  32000
#define BKX 64
#define G3  1536
#define EOS_ID 2

#define O1 16384000
#define O2 16392192
#define O3 16392256
#define O4 16392320

// ---------------- device state ----------------
__device__ float g_logits[(size_t)TT*BKX*VV];
__device__ float g_corr[TT*BKX];
__device__ float g_h[BKX*HH];
__device__ float g_hnew[BKX*HH];
__device__ int   g_inp[BKX];
__device__ float g_ss[BKX];
__device__ int   g_syms[TT*BKX];
__device__ int   g_preds[TT*BKX];
__device__ float g_scores[TT*BKX];
__device__ float g_hiddens[TT*BKX*HH];
__device__ float g_part[8*BKX*G3];
__device__ float g_tkv[BKX];
__device__ int   g_tksym[BKX];
__device__ int   g_tkpred[BKX];
__device__ int   g_src[TT*BKX];
__device__ int   g_seq[TT*BKX];
__device__ int   g_rowfin[TT*BB];
__device__ int   g_hcode[BB];

// ---------------- helpers ----------------
__device__ __forceinline__ unsigned long long ffma2(unsigned long long a,
                                                    unsigned long long b,
                                                    unsigned long long c){
    unsigned long long d;
    asm("fma.rn.f32x2 %0, %1, %2, %3;" : "=l"(d) : "l"(a), "l"(b), "l"(c));
    return d;
}
__device__ __forceinline__ unsigned long long dup2(float x){
    unsigned long long d; unsigned int xi = __float_as_uint(x);
    asm("mov.b64 %0, {%1, %2};" : "=l"(d) : "r"(xi), "r"(xi));
    return d;
}
__device__ __forceinline__ void unpack2(unsigned long long a, float& lo, float& hi){
    unsigned int l, h;
    asm("mov.b64 {%0, %1}, %2;" : "=r"(l), "=r"(h) : "l"(a));
    lo = __uint_as_float(l); hi = __uint_as_float(h);
}
__device__ __forceinline__ float neg_inf(){ return __int_as_float(0xff800000); }

// top-4 insert, order: value desc, index asc (jax.lax.top_k tie rule)
__device__ __forceinline__ void tk_insert(float* tv, int* ti, float val, int c){
    if (val > tv[3] || (val == tv[3] && c < ti[3])){
        tv[3] = val; ti[3] = c;
        #pragma unroll
        for (int j = 3; j > 0; j--){
            if (tv[j] > tv[j-1] || (tv[j] == tv[j-1] && ti[j] < ti[j-1])){
                float tf = tv[j]; tv[j] = tv[j-1]; tv[j-1] = tf;
                int   tq = ti[j]; ti[j] = ti[j-1]; ti[j-1] = tq;
            }
        }
    }
}
// sort 4 (value desc, index asc) via selection sort
__device__ __forceinline__ void sort4(float* v, int* id){
    #pragma unroll
    for (int i = 0; i < 4; i++){
        int best = i;
        #pragma unroll
        for (int j = i+1; j < 4; j++)
            if (v[j] > v[best] || (v[j] == v[best] && id[j] < id[best])) best = j;
        float tv = v[i]; v[i] = v[best]; v[best] = tv;
        int   tq = id[i]; id[i] = id[best]; id[best] = tq;
    }
}

// ---------------- init ----------------
__global__ void k_init(const float* __restrict__ enc_h){
    int i = blockIdx.x*blockDim.x + threadIdx.x;
    if (i < BKX*HH){
        int bk = i >> 9, u = i & (HH-1);
        g_h[i] = enc_h[(bk & (BB-1))*HH + u];
    }
    if (i < BKX){
        g_inp[i] = 1;
        g_ss[i]  = ((i & 3) == 0) ? 0.0f : neg_inf();
    }
}

// ---------------- GRU GEMM, split-K x4, 2 matrices ----------------
// grid 96 = 2 mats * 12 col-tiles(128) * 4 k-splits(128), 128 threads
__global__ void __launch_bounds__(128) k_gru_gemm(const float* __restrict__ E,
                                                  const float* __restrict__ Wih,
                                                  const float* __restrict__ Whh){
    __shared__ __align__(16) float a_t[128][68];
    int bid = blockIdx.x;
    int m   = bid / 48;
    int rem = bid % 48;
    int ct  = rem >> 2;
    int ks  = rem & 3;
    int c0  = ct * 128;
    int r0  = ks * 128;
    int tid = threadIdx.x;

    // stage transposed activations: conflict-free smem writes
    {
        int row = tid & 63;
        int rcb = tid >> 6;     // 0..1
        int sym = (m == 0) ? g_inp[row] : 0;
        for (int rc = rcb; rc < 128; rc += 2){
            float v;
            if (m == 0) v = E[(size_t)sym*HH + r0 + rc];
            else        v = g_h[row*HH + r0 + rc];
            a_t[rc][row] = v;
        }
    }
    __syncthreads();

    int col = c0 + tid;
    const float* W  = (m == 0) ? Wih : Whh;
    const float* wp = W + (size_t)r0*G3 + col;

    unsigned long long acc[32];
    #pragma unroll
    for (int q = 0; q < 32; q++) acc[q] = 0ULL;

    float wbuf[4];
    #pragma unroll
    for (int q = 0; q < 4; q++) wbuf[q] = wp[(size_t)q*G3];

    for (int r = 0; r < 128; r += 4){
        float wn[4];
        #pragma unroll
        for (int q = 0; q < 4; q++) wn[q] = wp[(size_t)((r+4+q) & 127)*G3];
        #pragma unroll
        for (int q = 0; q < 4; q++){
            unsigned long long w2 = dup2(wbuf[q]);
            const double2* ap = (const double2*)(&a_t[r+q][0]);
            #pragma unroll
            for (int p = 0; p < 16; p++){
                double2 d = ap[p];
                acc[2*p]   = ffma2(__double_as_longlong(d.x), w2, acc[2*p]);
                acc[2*p+1] = ffma2(__double_as_longlong(d.y), w2, acc[2*p+1]);
            }
        }
        #pragma unroll
        for (int q = 0; q < 4; q++) wbuf[q] = wn[q];
    }

    float* outp = g_part + (size_t)((m*4+ks)*BKX)*G3 + col;
    #pragma unroll
    for (int q = 0; q < 32; q++){
        float f0, f1; unpack2(acc[q], f0, f1);
        outp[(size_t)(2*q)*G3]   = f0;
        outp[(size_t)(2*q+1)*G3] = f1;
    }
}

// ---------------- GRU combine (gates) ----------------
__global__ void k_gru_combine(const float* __restrict__ bih, const float* __restrict__ bhh){
    int gid = blockIdx.x*256 + threadIdx.x;      // 32768
    if (gid >= BKX*HH) return;
    int bk = gid >> 9, u = gid & (HH-1);
    float gir = bih[u], giz = bih[HH+u], gin = bih[2*HH+u];
    float ghr = bhh[u], ghz = bhh[HH+u], ghn = bhh[2*HH+u];
    #pragma unroll
    for (int ks = 0; ks < 4; ks++){
        const float* p0 = g_part + (size_t)(ks*BKX + bk)*G3;
        const float* p1 = g_part + (size_t)((4+ks)*BKX + bk)*G3;
        gir += p0[u]; giz += p0[HH+u]; gin += p0[2*HH+u];
        ghr += p1[u]; ghz += p1[HH+u]; ghn += p1[2*HH+u];
    }
    float r = 1.0f/(1.0f + expf(-(gir + ghr)));
    float z = 1.0f/(1.0f + expf(-(giz + ghz)));
    float n = tanhf(gin + r*ghn);
    g_hnew[gid] = (1.0f - z)*n + z*g_h[gid];
}

// ---------------- logits GEMM: (64x512)@(512x32000) + bo ----------------
// grid 125, 256 threads, 1 column/thread, 64 rows as 32 f32x2 accumulators
__global__ void __launch_bounds__(256) k_logits(const float* __restrict__ Wo,
                                                const float* __restrict__ bo, int t){
    extern __shared__ float ht[];   // [512][68] transposed h_new
    int tid = threadIdx.x;
    {
        int row = tid & 63;
        int rcb = tid >> 6;         // 0..3
        for (int rc = rcb; rc < HH; rc += 4)
            ht[rc*68 + row] = g_hnew[row*HH + rc];
    }
    __syncthreads();

    int v = blockIdx.x*256 + tid;
    unsigned long long acc[32];
    #pragma unroll
    for (int q = 0; q < 32; q++) acc[q] = 0ULL;

    const float* wp = Wo + v;
    float wbuf[4];
    #pragma unroll
    for (int q = 0; q < 4; q++) wbuf[q] = wp[(size_t)q*VV];

    for (int r = 0; r < HH; r += 4){
        float wn[4];
        #pragma unroll
        for (int q = 0; q < 4; q++) wn[q] = wp[(size_t)((r+4+q) & (HH-1))*VV];
        #pragma unroll
        for (int q = 0; q < 4; q++){
            unsigned long long w2 = dup2(wbuf[q]);
            const double2* ap = (const double2*)(&ht[(r+q)*68]);
            #pragma unroll
            for (int p = 0; p < 16; p++){
                double2 d = ap[p];
                acc[2*p]   = ffma2(__double_as_longlong(d.x), w2, acc[2*p]);
                acc[2*p+1] = ffma2(__double_as_longlong(d.y), w2, acc[2*p+1]);
            }
        }
        #pragma unroll
        for (int q = 0; q < 4; q++) wbuf[q] = wn[q];
    }

    float bv = bo[v];
    float* gl = g_logits + (size_t)(t*BKX)*VV + v;
    #pragma unroll
    for (int q = 0; q < 32; q++){
        float f0, f1; unpack2(acc[q], f0, f1);
        gl[(size_t)(2*q)*VV]   = f0 + bv;
        gl[(size_t)(2*q+1)*VV] = f1 + bv;
    }
}

// ---------------- log-softmax correction per row ----------------
__global__ void __launch_bounds__(256) k_rowstats(int t){
    __shared__ float red[256];
    int row = blockIdx.x;
    int tid = threadIdx.x;
    const float* p = g_logits + (size_t)(t*BKX + row)*VV;
    float m = neg_inf();
    for (int v = tid; v < VV; v += 256) m = fmaxf(m, p[v]);
    red[tid] = m; __syncthreads();
    for (int s = 128; s > 0; s >>= 1){
        if (tid < s) red[tid] = fmaxf(red[tid], red[tid+s]);
        __syncthreads();
    }
    m = red[0]; __syncthreads();
    float sum = 0.0f;
    for (int v = tid; v < VV; v += 256) sum += expf(p[v] - m);
    red[tid] = sum; __syncthreads();
    for (int s = 128; s > 0; s >>= 1){
        if (tid < s) red[tid] += red[tid+s];
        __syncthreads();
    }
    if (tid == 0) g_corr[t*BKX + row] = m + logf(red[0]);
}

// ---------------- per-batch top-4 over K*V candidates ----------------
__global__ void __launch_bounds__(256) k_topk(int t){
    __shared__ float sv[1024];
    __shared__ int   si[1024];
    int b = blockIdx.x, tid = threadIdx.x;
    float tv[4]; int ti[4];
    #pragma unroll
    for (int i = 0; i < 4; i++){ tv[i] = neg_inf(); ti[i] = 0x7fffffff; }

    #pragma unroll
    for (int k = 0; k < KK; k++){
        int row = b*KK + k;
        float base = g_ss[row] - g_corr[t*BKX + row];
        const float* p = g_logits + (size_t)(t*BKX + row)*VV;
        for (int v = tid; v < VV; v += 256)
            tk_insert(tv, ti, base + p[v], k*VV + v);
    }
    #pragma unroll
    for (int i = 0; i < 4; i++){ sv[tid*4+i] = tv[i]; si[tid*4+i] = ti[i]; }
    __syncthreads();
    if (tid < 32){
        float mv[4]; int mi[4];
        #pragma unroll
        for (int i = 0; i < 4; i++){ mv[i] = neg_inf(); mi[i] = 0x7fffffff; }
        for (int q = tid*32; q < tid*32+32; q++) tk_insert(mv, mi, sv[q], si[q]);
        #pragma unroll
        for (int i = 0; i < 4; i++){ sv[tid*4+i] = mv[i]; si[tid*4+i] = mi[i]; }
    }
    __syncthreads();
    if (tid == 0){
        float fv[4]; int fi[4];
        #pragma unroll
        for (int i = 0; i < 4; i++){ fv[i] = neg_inf(); fi[i] = 0x7fffffff; }
        for (int q = 0; q < 128; q++) tk_insert(fv, fi, sv[q], si[q]);
        #pragma unroll
        for (int k = 0; k < 4; k++){
            g_tkv[b*KK+k]    = fv[k];
            g_tksym[b*KK+k]  = fi[k] % VV;
            g_tkpred[b*KK+k] = fi[k] / VV + b*KK;
        }
    }
}

// ---------------- beam selection / state update ----------------
__global__ void __launch_bounds__(128) k_select(int t){
    int j = blockIdx.x;
    int tid = threadIdx.x;
    int pred = g_tkpred[j];
    for (int u = tid; u < HH; u += 128){
        float hv = g_hnew[pred*HH + u];
        g_h[j*HH + u] = hv;
        g_hiddens[(size_t)(t*BKX + j)*HH + u] = hv;
    }
    if (tid == 0){
        int sym = g_tksym[j];
        float sc = g_tkv[j];
        g_syms[t*BKX + j]   = sym;
        g_preds[t*BKX + j]  = pred;
        g_scores[t*BKX + j] = sc;
        g_ss[j]  = (sym == EOS_ID) ? neg_inf() : sc;
        g_inp[j] = sym;
    }
}

// ---------------- backward trace + small outputs ----------------
__global__ void __launch_bounds__(64) k_backward(float* __restrict__ out){
    __shared__ float s_s[64]; __shared__ int s_len[64]; __shared__ int s_hc[64];
    __shared__ int s_tp[64]; __shared__ int s_eosf[16];
    __shared__ int sym[64], prd[64]; __shared__ float scr[64];
    __shared__ int sid[64]; __shared__ float s0v[64];
    __shared__ int re[64];

    int r  = threadIdx.x;
    int b  = r >> 2;
    int kk = r & 3;

    if (kk == 0){
        float v[4]; int id[4];
        #pragma unroll
        for (int k = 0; k < 4; k++){ v[k] = g_scores[(TT-1)*BKX + b*4 + k]; id[k] = k; }
        sort4(v, id);
        #pragma unroll
        for (int k = 0; k < 4; k++){ sid[b*4+k] = id[k]; s0v[b*4+k] = v[k]; }
        s_eosf[b] = 0;
    }
    __syncthreads();
    s_tp[r]  = b*4 + sid[r];
    s_s[r]   = s0v[r];
    s_len[r] = TT;
    s_hc[r]  = -1;
    __syncthreads();

    for (int t = TT-1; t >= 0; t--){
        sym[r] = g_syms[t*BKX + r];
        prd[r] = g_preds[t*BKX + r];
        scr[r] = g_scores[t*BKX + r];
        __syncthreads();

        int src    = s_tp[r];
        int my_src = src;
        int my_sym = sym[src];
        int my_np  = prd[src];

        int eosf = s_eosf[b];
        int cnt  = 0;
        #pragma unroll
        for (int kq = 0; kq < 4; kq++) cnt += (sym[b*4+kq] == EOS_ID);

        #pragma unroll
        for (int kj = 0; kj < 4; kj++){
            int j = b*4 + kj;
            if (sym[j] == EOS_ID){
                int higher = 0;
                for (int kq = kj+1; kq < 4; kq++) higher += (sym[b*4+kq] == EOS_ID);
                int occ   = eosf + higher;
                int res_k = 3 - (occ & 3);
                if (res_k == kk){
                    my_src = j; my_sym = sym[j]; my_np = prd[j];
                    s_hc[r]  = t*BKX + j;
                    s_s[r]   = scr[j];
                    s_len[r] = t + 1;
                }
            }
        }
        g_src[t*BKX + r] = my_src;
        g_seq[t*BKX + r] = my_sym;
        __syncthreads();
        s_tp[r] = my_np;
        if (kk == 0) s_eosf[b] = eosf + cnt;
        __syncthreads();
    }

    // final re-rank
    if (kk == 0){
        float v[4]; int id[4];
        #pragma unroll
        for (int k = 0; k < 4; k++){ v[k] = s_s[b*4+k]; id[k] = k; }
        sort4(v, id);
        #pragma unroll
        for (int k = 0; k < 4; k++){
            re[b*4+k] = b*4 + id[k];
            out[O2 + b*4+k] = v[k];
        }
    }
    __syncthreads();
    out[O3 + r] = (float)s_len[re[r]];
    for (int t = 0; t < TT; t++)
        out[O4 + (t*BB + b)*KK + kk] = (float)g_seq[t*BKX + re[r]];
    if (kk == 0){
        int r0 = re[b*4];
        for (int t = 0; t < TT; t++)
            g_rowfin[t*BB + b] = g_src[t*BKX + r0];
        g_hcode[b] = s_hc[r0];
    }
}

// ---------------- big outputs ----------------
__global__ void k_out_hidden(float* __restrict__ out){
    int b = blockIdx.x, u = threadIdx.x;
    int code = g_hcode[b];
    out[O1 + b*HH + u] = (code < 0) ? 0.0f : g_hiddens[(size_t)code*HH + u];
}

__global__ void __launch_bounds__(256) k_out_logits(float* __restrict__ out){
    size_t idx = (size_t)blockIdx.x*256 + threadIdx.x;
    if (idx >= (size_t)TT*BB*VV) return;
    int t = (int)(idx / ((size_t)BB*VV));
    int rem = (int)(idx - (size_t)t*BB*VV);
    int bb = rem / VV;
    int v  = rem - bb*VV;
    int row = g_rowfin[t*BB + bb];
    out[idx] = g_logits[(size_t)(t*BKX + row)*VV + v] - g_corr[t*BKX + row];
}

// ---------------- launch ----------------
extern "C" void kernel_launch(void* const* d_in, const int* in_sizes, int n_in,
                              void* d_out, int out_size){
    const float* enc_h = (const float*)d_in[0];
    const float* E     = (const float*)d_in[1];
    const float* Wih   = (const float*)d_in[2];
    const float* Whh   = (const float*)d_in[3];
    const float* bih   = (const float*)d_in[4];
    const float* bhh   = (const float*)d_in[5];
    const float* Wo    = (const float*)d_in[6];
    const float* bo    = (const float*)d_in[7];
    float* out = (float*)d_out;

    const int LOGITS_SMEM = HH*68*sizeof(float);   // 139264
    cudaFuncSetAttribute(k_logits, cudaFuncAttributeMaxDynamicSharedMemorySize, LOGITS_SMEM);

    k_init<<<128, 256>>>(enc_h);
    for (int t = 0; t < TT; t++){
        k_gru_gemm<<<96, 128>>>(E, Wih, Whh);
        k_gru_combine<<<128, 256>>>(bih, bhh);
        k_logits<<<125, 256, LOGITS_SMEM>>>(Wo, bo, t);
        k_rowstats<<<64, 256>>>(t);
        k_topk<<<16, 256>>>(t);
        k_select<<<64, 128>>>(t);
    }
    k_backward<<<1, 64>>>(out);
    k_out_hidden<<<BB, HH>>>(out);
    k_out_logits<<<(TT*BB*VV + 255)/256, 256>>>(out);
}